// round 1
// baseline (speedup 1.0000x reference)
#include <cuda_runtime.h>
#include <math.h>

#define NB 4
#define NS 4000
#define NDIN 1024
#define NDA 512
#define NL 8921

// Scratch (allocation-free rule: device globals)
__device__ float g_z[NB * NS * NDA];   // 32.8 MB : z = tanh(xW^T + b)
__device__ float g_m[NB * NL * NDA];   // 73.1 MB : per-label context vectors

// ---------------------------------------------------------------------------
// Generic 128x128x16 SGEMM, 8x8 microtile, 256 threads.
// A is always [M,K] row-major. B is [N,K] (BNT=true, dot-of-rows) or [K,N].
// Optional epilogue: C = tanh(acc + bias[n]).
// batch via blockIdx.z with element strides sA/sB/sC.
// Requires K % 16 == 0, N % 4 == 0 (holds: K in {1024,512,4000}, N in {512,4000}).
// ---------------------------------------------------------------------------
template <bool BNT, bool TANHBIAS>
__global__ __launch_bounds__(256)
void gemm128(const float* __restrict__ A, const float* __restrict__ Bm,
             float* __restrict__ C, const float* __restrict__ bias,
             int M, int N, int K,
             long long sA, long long sB, long long sC)
{
    __shared__ float As[16][132];
    __shared__ float Bs[16][132];

    const float* Ab = A  + (long long)blockIdx.z * sA;
    const float* Bb = Bm + (long long)blockIdx.z * sB;
    float*       Cb = C  + (long long)blockIdx.z * sC;

    const int m0 = blockIdx.y * 128;
    const int n0 = blockIdx.x * 128;
    const int t  = threadIdx.x;
    const int tx = t & 15;
    const int ty = t >> 4;

    float acc[8][8];
#pragma unroll
    for (int i = 0; i < 8; i++)
#pragma unroll
        for (int j = 0; j < 8; j++) acc[i][j] = 0.f;

    for (int k0 = 0; k0 < K; k0 += 16) {
        __syncthreads();
        // A tile -> As[k][m] (transpose on load)
#pragma unroll
        for (int h = 0; h < 2; h++) {
            int row = (t >> 2) + h * 64;
            int kc  = (t & 3) * 4;
            int gm  = m0 + row;
            float4 v = make_float4(0.f, 0.f, 0.f, 0.f);
            if (gm < M) v = *(const float4*)(Ab + (long long)gm * K + (k0 + kc));
            As[kc + 0][row] = v.x; As[kc + 1][row] = v.y;
            As[kc + 2][row] = v.z; As[kc + 3][row] = v.w;
        }
        if (BNT) {
#pragma unroll
            for (int h = 0; h < 2; h++) {
                int row = (t >> 2) + h * 64;
                int kc  = (t & 3) * 4;
                int gn  = n0 + row;
                float4 v = make_float4(0.f, 0.f, 0.f, 0.f);
                if (gn < N) v = *(const float4*)(Bb + (long long)gn * K + (k0 + kc));
                Bs[kc + 0][row] = v.x; Bs[kc + 1][row] = v.y;
                Bs[kc + 2][row] = v.z; Bs[kc + 3][row] = v.w;
            }
        } else {
#pragma unroll
            for (int h = 0; h < 2; h++) {
                int kk = (t >> 5) + h * 8;
                int nc = (t & 31) * 4;
                int gn = n0 + nc;
                float4 v = make_float4(0.f, 0.f, 0.f, 0.f);
                if (gn < N) v = *(const float4*)(Bb + (long long)(k0 + kk) * N + gn);
                *(float4*)&Bs[kk][nc] = v;
            }
        }
        __syncthreads();

#pragma unroll
        for (int k = 0; k < 16; k++) {
            float a[8], b[8];
            float4 a0 = *(const float4*)&As[k][ty * 4];
            float4 a1 = *(const float4*)&As[k][64 + ty * 4];
            float4 b0 = *(const float4*)&Bs[k][tx * 4];
            float4 b1 = *(const float4*)&Bs[k][64 + tx * 4];
            a[0] = a0.x; a[1] = a0.y; a[2] = a0.z; a[3] = a0.w;
            a[4] = a1.x; a[5] = a1.y; a[6] = a1.z; a[7] = a1.w;
            b[0] = b0.x; b[1] = b0.y; b[2] = b0.z; b[3] = b0.w;
            b[4] = b1.x; b[5] = b1.y; b[6] = b1.z; b[7] = b1.w;
#pragma unroll
            for (int i = 0; i < 8; i++)
#pragma unroll
                for (int j = 0; j < 8; j++)
                    acc[i][j] = fmaf(a[i], b[j], acc[i][j]);
        }
    }

#pragma unroll
    for (int i = 0; i < 8; i++) {
        int row = m0 + ((i < 4) ? (ty * 4 + i) : (64 + ty * 4 + (i - 4)));
        if (row >= M) continue;
#pragma unroll
        for (int jj = 0; jj < 2; jj++) {
            int c0 = n0 + ((jj == 0) ? (tx * 4) : (64 + tx * 4));
            if (c0 >= N) continue;   // N % 4 == 0 so full float4 is in-bounds
            float4 v;
            v.x = acc[i][jj * 4 + 0]; v.y = acc[i][jj * 4 + 1];
            v.z = acc[i][jj * 4 + 2]; v.w = acc[i][jj * 4 + 3];
            if (TANHBIAS) {
                float4 bb = *(const float4*)(bias + c0);
                v.x = tanhf(v.x + bb.x); v.y = tanhf(v.y + bb.y);
                v.z = tanhf(v.z + bb.z); v.w = tanhf(v.w + bb.w);
            }
            *(float4*)(Cb + (long long)row * N + c0) = v;
        }
    }
}

// ---------------------------------------------------------------------------
// In-place softmax over the last dim (length NS) — one block per (b,l) row.
// Row is staged in smem: exactly 1 HBM read + 1 HBM write of the 571 MB array.
// ---------------------------------------------------------------------------
__global__ __launch_bounds__(256)
void softmax_kernel(float* __restrict__ alpha)
{
    __shared__ float buf[NS];
    __shared__ float red[8];
    float* p = alpha + (long long)blockIdx.x * NS;
    const int t = threadIdx.x;
    const int lane = t & 31, wid = t >> 5;

    float mx = -3.4e38f;
    for (int i = t * 4; i < NS; i += 1024) {
        float4 v = *(const float4*)(p + i);
        *(float4*)(buf + i) = v;
        mx = fmaxf(fmaxf(mx, v.x), fmaxf(fmaxf(v.y, v.z), v.w));
    }
#pragma unroll
    for (int o = 16; o; o >>= 1) mx = fmaxf(mx, __shfl_xor_sync(0xffffffffu, mx, o));
    if (lane == 0) red[wid] = mx;
    __syncthreads();
    if (wid == 0) {
        float m2 = (lane < 8) ? red[lane] : -3.4e38f;
#pragma unroll
        for (int o = 4; o; o >>= 1) m2 = fmaxf(m2, __shfl_xor_sync(0xffffffffu, m2, o));
        if (lane == 0) red[0] = m2;
    }
    __syncthreads();
    mx = red[0];
    __syncthreads();

    float s = 0.f;
    for (int i = t * 4; i < NS; i += 1024) {
        float4 v = *(const float4*)(buf + i);
        v.x = expf(v.x - mx); v.y = expf(v.y - mx);
        v.z = expf(v.z - mx); v.w = expf(v.w - mx);
        *(float4*)(buf + i) = v;
        s += (v.x + v.y) + (v.z + v.w);
    }
#pragma unroll
    for (int o = 16; o; o >>= 1) s += __shfl_xor_sync(0xffffffffu, s, o);
    if (lane == 0) red[wid] = s;
    __syncthreads();
    if (wid == 0) {
        float s2 = (lane < 8) ? red[lane] : 0.f;
#pragma unroll
        for (int o = 4; o; o >>= 1) s2 += __shfl_xor_sync(0xffffffffu, s2, o);
        if (lane == 0) red[0] = s2;
    }
    __syncthreads();
    float inv = 1.f / red[0];

    for (int i = t * 4; i < NS; i += 1024) {
        float4 v = *(const float4*)(buf + i);
        v.x *= inv; v.y *= inv; v.z *= inv; v.w *= inv;
        *(float4*)(p + i) = v;
    }
}

// ---------------------------------------------------------------------------
// y[b,l] = dot(V[l], m[b,l]) + V_b[l].  One block (128 thr) per (b,l).
// ---------------------------------------------------------------------------
__global__ __launch_bounds__(128)
void y_kernel(const float* __restrict__ Vw, const float* __restrict__ Vb,
              const float* __restrict__ mbuf, float* __restrict__ y)
{
    __shared__ float red[4];
    const int row = blockIdx.x;      // b*NL + l
    const int l   = row % NL;
    const float* mr = mbuf + (long long)row * NDA;
    const float* vr = Vw   + (long long)l   * NDA;
    const int t = threadIdx.x;

    float s = 0.f;
    for (int i = t; i < NDA; i += 128) s = fmaf(vr[i], mr[i], s);
#pragma unroll
    for (int o = 16; o; o >>= 1) s += __shfl_xor_sync(0xffffffffu, s, o);
    const int lane = t & 31, wid = t >> 5;
    if (lane == 0) red[wid] = s;
    __syncthreads();
    if (t == 0) y[row] = ((red[0] + red[1]) + (red[2] + red[3])) + Vb[l];
}

// ---------------------------------------------------------------------------
extern "C" void kernel_launch(void* const* d_in, const int* in_sizes, int n_in,
                              void* d_out, int out_size)
{
    const float* x  = (const float*)d_in[0];   // [B,S,D_IN]
    const float* Ww = (const float*)d_in[1];   // [D_A,D_IN]
    const float* Wb = (const float*)d_in[2];   // [D_A]
    const float* Uw = (const float*)d_in[3];   // [L,D_A]
    const float* Vw = (const float*)d_in[4];   // [L,D_A]
    const float* Vb = (const float*)d_in[5];   // [L]

    float* y     = (float*)d_out;                      // [B,L]
    float* alpha = (float*)d_out + (size_t)NB * NL;    // [B,L,S]

    float *zbuf = nullptr, *mbuf = nullptr;
    cudaGetSymbolAddress((void**)&zbuf, g_z);
    cudaGetSymbolAddress((void**)&mbuf, g_m);

    // 1) z = tanh(x @ W^T + b)   [16000, 512]
    {
        dim3 g(NDA / 128, (NB * NS + 127) / 128, 1);
        gemm128<true, true><<<g, 256>>>(x, Ww, zbuf, Wb,
                                        NB * NS, NDA, NDIN, 0, 0, 0);
    }
    // 2) scores[b,l,s] = U @ z_b^T  -> written straight into alpha region
    {
        dim3 g((NS + 127) / 128, (NL + 127) / 128, NB);
        gemm128<true, false><<<g, 256>>>(Uw, zbuf, alpha, nullptr,
                                         NL, NS, NDA,
                                         0, (long long)NS * NDA, (long long)NL * NS);
    }
    // 3) softmax over S, in place
    softmax_kernel<<<NB * NL, 256>>>(alpha);

    // 4) m[b,l,:] = alpha_b @ z_b   [L, 512]
    {
        dim3 g(NDA / 128, (NL + 127) / 128, NB);
        gemm128<false, false><<<g, 256>>>(alpha, zbuf, mbuf, nullptr,
                                          NL, NDA, NS,
                                          (long long)NL * NS, (long long)NS * NDA,
                                          (long long)NL * NDA);
    }
    // 5) y[b,l] = <V[l], m[b,l]> + V_b[l]
    y_kernel<<<NB * NL, 128>>>(Vw, Vb, mbuf, y);
}

// round 3
// speedup vs baseline: 2.0284x; 2.0284x over previous
#include <cuda_runtime.h>
#include <cuda_bf16.h>
#include <math.h>
#include <stdint.h>

#define NB 4
#define NS 4000
#define NDIN 1024
#define NDA 512
#define NL 8921
#define SPAD 4096   // padded S
#define LPAD 8960   // padded L (70 * 128)
#define KCH 32      // bf16 K elements per pipeline chunk
#define STG 32768   // bytes per pipeline stage (4 x 8KB buffers)

// ---------------------------------------------------------------------------
// Scratch (device globals: zero-initialized at module load; padded regions are
// never written so they stay zero -> no bounds checks in GEMM operand loads).
// ---------------------------------------------------------------------------
__device__ float g_z[(size_t)NB * NS * NDA];
__device__ __nv_bfloat16 g_zhi[(size_t)NB * SPAD * NDA];   // z hi  [b][s][a]
__device__ __nv_bfloat16 g_zlo[(size_t)NB * SPAD * NDA];   // z lo
__device__ __nv_bfloat16 g_zThi[(size_t)NB * NDA * SPAD];  // z^T hi [b][a][s]
__device__ __nv_bfloat16 g_zTlo[(size_t)NB * NDA * SPAD];  // z^T lo
__device__ __nv_bfloat16 g_Uhi[(size_t)LPAD * NDA];
__device__ __nv_bfloat16 g_Ulo[(size_t)LPAD * NDA];
__device__ __nv_bfloat16 g_ahi[(size_t)NB * LPAD * SPAD];  // alpha hi (padded)
__device__ __nv_bfloat16 g_alo[(size_t)NB * LPAD * SPAD];  // alpha lo
__device__ float g_m[(size_t)NB * NL * NDA];

// ---------------------------------------------------------------------------
// Helpers
// ---------------------------------------------------------------------------
__device__ __forceinline__ uint32_t smem_u32(const void* p) {
    uint32_t a;
    asm("{ .reg .u64 t; cvta.to.shared.u64 t, %1; cvt.u32.u64 %0, t; }"
        : "=r"(a) : "l"(p));
    return a;
}
__device__ __forceinline__ void cpa16(uint32_t dst, const void* src) {
    asm volatile("cp.async.cg.shared.global [%0], [%1], 16;"
                 :: "r"(dst), "l"(src) : "memory");
}
#define CP_COMMIT() asm volatile("cp.async.commit_group;" ::: "memory")
#define CP_WAIT(n)  asm volatile("cp.async.wait_group %0;" :: "n"(n) : "memory")

__device__ __forceinline__ void ldsm4(uint32_t& r0, uint32_t& r1,
                                      uint32_t& r2, uint32_t& r3, uint32_t addr) {
    asm volatile("ldmatrix.sync.aligned.m8n8.x4.shared.b16 {%0,%1,%2,%3}, [%4];"
                 : "=r"(r0), "=r"(r1), "=r"(r2), "=r"(r3) : "r"(addr));
}
__device__ __forceinline__ void mma16816(float* d, const uint32_t* a, const uint32_t* b) {
    asm volatile(
        "mma.sync.aligned.m16n8k16.row.col.f32.bf16.bf16.f32 "
        "{%0,%1,%2,%3}, {%4,%5,%6,%7}, {%8,%9}, {%0,%1,%2,%3};"
        : "+f"(d[0]), "+f"(d[1]), "+f"(d[2]), "+f"(d[3])
        : "r"(a[0]), "r"(a[1]), "r"(a[2]), "r"(a[3]), "r"(b[0]), "r"(b[1]));
}

__device__ __forceinline__ void split_bf16(float v, __nv_bfloat16& hi, __nv_bfloat16& lo) {
    hi = __float2bfloat16(v);
    lo = __float2bfloat16(v - __bfloat162float(hi));
}
__device__ __forceinline__ uint32_t pack2(__nv_bfloat16 a, __nv_bfloat16 b) {
    return (uint32_t)__bfloat16_as_ushort(a) | ((uint32_t)__bfloat16_as_ushort(b) << 16);
}

// Swizzled smem offset inside one 128x32 bf16 buffer (64B rows, 4x16B groups;
// group = c16 ^ ((row>>1)&3) -> the 8 rows of any ldmatrix phase hit 8
// distinct 16B slots mod 128B => conflict-free).
__device__ __forceinline__ uint32_t swoff(int row, int c16) {
    return (uint32_t)(row * 64 + ((c16 ^ ((row >> 1) & 3)) * 16));
}

// ---------------------------------------------------------------------------
// bf16x3 tensor-core GEMM via mma.sync:
//   D[M,N] = sum_k (Ahi+Alo)[m,k]*(Bhi+Blo)[n,k]   (Alo*Blo dropped)
// CTA tile 128x128, 8 warps (2x4), warp tile 64x32, K-chunk 32, 2-stage
// cp.async double buffer. fp32 accumulators in registers.
// ---------------------------------------------------------------------------
__global__ __launch_bounds__(256, 1)
void gemm_mma(const __nv_bfloat16* __restrict__ Ahi, const __nv_bfloat16* __restrict__ Alo,
              const __nv_bfloat16* __restrict__ Bhi, const __nv_bfloat16* __restrict__ Blo,
              float* __restrict__ C,
              int nk, int Mvalid, int Nvalid, int ldA, int ldB, int ldC,
              long long sA, long long sB, long long sC)
{
    extern __shared__ char smem[];
    const uint32_t sb = smem_u32(smem);

    const int t = threadIdx.x, w = t >> 5, lane = t & 31;
    const int m0 = blockIdx.y * 128, n0 = blockIdx.x * 128, b = blockIdx.z;
    const int wm = (w >> 2) * 64, wn = (w & 3) * 32;

    const __nv_bfloat16* Ah = Ahi + b * sA + (long long)m0 * ldA;
    const __nv_bfloat16* Al = Alo + b * sA + (long long)m0 * ldA;
    const __nv_bfloat16* Bh = Bhi + b * sB + (long long)n0 * ldB;
    const __nv_bfloat16* Bl = Blo + b * sB + (long long)n0 * ldB;
    float* Cb = C + b * sC;

    float acc[4][4][4];
#pragma unroll
    for (int i = 0; i < 4; i++)
#pragma unroll
        for (int j = 0; j < 4; j++)
#pragma unroll
            for (int q = 0; q < 4; q++) acc[i][j][q] = 0.f;

    // stage layout: +0 Ahi, +8192 Alo, +16384 Bhi, +24576 Blo
    auto load_stage = [&](int c, int s) {
        const uint32_t st = sb + s * STG;
        const int kb = c * KCH;
#pragma unroll
        for (int j = 0; j < 8; j++) {
            const int buf = j >> 1;                       // compile-time per j
            const int cid = t + 256 * (j & 1);            // 0..511
            const int row = cid >> 2, c16 = cid & 3;
            const uint32_t dst = st + buf * 8192 + swoff(row, c16);
            if (buf == 0)      cpa16(dst, Ah + (long long)row * ldA + kb + c16 * 8);
            else if (buf == 1) cpa16(dst, Al + (long long)row * ldA + kb + c16 * 8);
            else if (buf == 2) cpa16(dst, Bh + (long long)row * ldB + kb + c16 * 8);
            else               cpa16(dst, Bl + (long long)row * ldB + kb + c16 * 8);
        }
    };

    load_stage(0, 0);
    CP_COMMIT();

    for (int c = 0; c < nk; c++) {
        const int s = c & 1;
        if (c + 1 < nk) {
            load_stage(c + 1, s ^ 1);
            CP_COMMIT();
            CP_WAIT(1);
        } else {
            CP_WAIT(0);
        }
        __syncthreads();

        const uint32_t stAh = sb + s * STG;
        const uint32_t stAl = stAh + 8192;
        const uint32_t stBh = stAh + 16384;
        const uint32_t stBl = stAh + 24576;

#pragma unroll
        for (int kk = 0; kk < 2; kk++) {
            uint32_t ah[4][4], al[4][4];
            {
                const int r = lane & 15, ch = lane >> 4;
#pragma unroll
                for (int mt = 0; mt < 4; mt++) {
                    const int row = wm + mt * 16 + r;
                    const uint32_t off = swoff(row, kk * 2 + ch);
                    ldsm4(ah[mt][0], ah[mt][1], ah[mt][2], ah[mt][3], stAh + off);
                    ldsm4(al[mt][0], al[mt][1], al[mt][2], al[mt][3], stAl + off);
                }
            }
            uint32_t bh[4][2], bl[4][2];
            {
                const int r8 = ((lane >> 4) << 3) + (lane & 7);
                const int ch = (lane >> 3) & 1;
#pragma unroll
                for (int nh = 0; nh < 2; nh++) {
                    const int row = wn + nh * 16 + r8;
                    const uint32_t off = swoff(row, kk * 2 + ch);
                    uint32_t r0, r1, r2, r3;
                    ldsm4(r0, r1, r2, r3, stBh + off);
                    bh[nh * 2][0] = r0; bh[nh * 2][1] = r1;
                    bh[nh * 2 + 1][0] = r2; bh[nh * 2 + 1][1] = r3;
                    ldsm4(r0, r1, r2, r3, stBl + off);
                    bl[nh * 2][0] = r0; bl[nh * 2][1] = r1;
                    bl[nh * 2 + 1][0] = r2; bl[nh * 2 + 1][1] = r3;
                }
            }
#pragma unroll
            for (int mt = 0; mt < 4; mt++)
#pragma unroll
                for (int nt = 0; nt < 4; nt++) {
                    mma16816(acc[mt][nt], ah[mt], bh[nt]);
                    mma16816(acc[mt][nt], al[mt], bh[nt]);
                    mma16816(acc[mt][nt], ah[mt], bl[nt]);
                }
        }
        __syncthreads();
    }

    // Epilogue: fp32 stores, 8-float (32B) aligned segments per quad.
#pragma unroll
    for (int mt = 0; mt < 4; mt++) {
        const int r0g = m0 + wm + mt * 16 + (lane >> 2);
        const int r1g = r0g + 8;
#pragma unroll
        for (int nt = 0; nt < 4; nt++) {
            const int cg = n0 + wn + nt * 8 + (lane & 3) * 2;
            if (cg < Nvalid) {
                if (r0g < Mvalid) {
                    float2 v = make_float2(acc[mt][nt][0], acc[mt][nt][1]);
                    *(float2*)(Cb + (long long)r0g * ldC + cg) = v;
                }
                if (r1g < Mvalid) {
                    float2 v = make_float2(acc[mt][nt][2], acc[mt][nt][3]);
                    *(float2*)(Cb + (long long)r1g * ldC + cg) = v;
                }
            }
        }
    }
}

// ---------------------------------------------------------------------------
// fp32 SGEMM for z = tanh(x W^T + b): 128x128x16, 8x8 microtile (proven in R1)
// ---------------------------------------------------------------------------
__global__ __launch_bounds__(256)
void gemm_z(const float* __restrict__ A, const float* __restrict__ Bm,
            float* __restrict__ C, const float* __restrict__ bias,
            int M, int N, int K)
{
    __shared__ float As[16][132];
    __shared__ float Bs[16][132];

    const int m0 = blockIdx.y * 128;
    const int n0 = blockIdx.x * 128;
    const int t = threadIdx.x;
    const int tx = t & 15;
    const int ty = t >> 4;

    float acc[8][8];
#pragma unroll
    for (int i = 0; i < 8; i++)
#pragma unroll
        for (int j = 0; j < 8; j++) acc[i][j] = 0.f;

    for (int k0 = 0; k0 < K; k0 += 16) {
        __syncthreads();
#pragma unroll
        for (int h = 0; h < 2; h++) {
            int row = (t >> 2) + h * 64;
            int kc = (t & 3) * 4;
            int gm = m0 + row;
            float4 v = make_float4(0.f, 0.f, 0.f, 0.f);
            if (gm < M) v = *(const float4*)(A + (long long)gm * K + (k0 + kc));
            As[kc + 0][row] = v.x; As[kc + 1][row] = v.y;
            As[kc + 2][row] = v.z; As[kc + 3][row] = v.w;
        }
#pragma unroll
        for (int h = 0; h < 2; h++) {
            int row = (t >> 2) + h * 64;
            int kc = (t & 3) * 4;
            int gn = n0 + row;
            float4 v = make_float4(0.f, 0.f, 0.f, 0.f);
            if (gn < N) v = *(const float4*)(Bm + (long long)gn * K + (k0 + kc));
            Bs[kc + 0][row] = v.x; Bs[kc + 1][row] = v.y;
            Bs[kc + 2][row] = v.z; Bs[kc + 3][row] = v.w;
        }
        __syncthreads();

#pragma unroll
        for (int k = 0; k < 16; k++) {
            float a[8], b[8];
            float4 a0 = *(const float4*)&As[k][ty * 4];
            float4 a1 = *(const float4*)&As[k][64 + ty * 4];
            float4 b0 = *(const float4*)&Bs[k][tx * 4];
            float4 b1 = *(const float4*)&Bs[k][64 + tx * 4];
            a[0] = a0.x; a[1] = a0.y; a[2] = a0.z; a[3] = a0.w;
            a[4] = a1.x; a[5] = a1.y; a[6] = a1.z; a[7] = a1.w;
            b[0] = b0.x; b[1] = b0.y; b[2] = b0.z; b[3] = b0.w;
            b[4] = b1.x; b[5] = b1.y; b[6] = b1.z; b[7] = b1.w;
#pragma unroll
            for (int i = 0; i < 8; i++)
#pragma unroll
                for (int j = 0; j < 8; j++)
                    acc[i][j] = fmaf(a[i], b[j], acc[i][j]);
        }
    }

#pragma unroll
    for (int i = 0; i < 8; i++) {
        int row = m0 + ((i < 4) ? (ty * 4 + i) : (64 + ty * 4 + (i - 4)));
        if (row >= M) continue;
#pragma unroll
        for (int jj = 0; jj < 2; jj++) {
            int c0 = n0 + ((jj == 0) ? (tx * 4) : (64 + tx * 4));
            if (c0 >= N) continue;
            float4 v;
            v.x = acc[i][jj * 4 + 0]; v.y = acc[i][jj * 4 + 1];
            v.z = acc[i][jj * 4 + 2]; v.w = acc[i][jj * 4 + 3];
            float4 bb = *(const float4*)(bias + c0);
            v.x = tanhf(v.x + bb.x); v.y = tanhf(v.y + bb.y);
            v.z = tanhf(v.z + bb.z); v.w = tanhf(v.w + bb.w);
            *(float4*)(C + (long long)row * N + c0) = v;
        }
    }
}

// ---------------------------------------------------------------------------
// z fp32 -> bf16 hi/lo (padded row-major) + transposed hi/lo
// ---------------------------------------------------------------------------
__global__ __launch_bounds__(256)
void zconv(const float* __restrict__ z)
{
    __shared__ __nv_bfloat16 shi[32][33];
    __shared__ __nv_bfloat16 slo[32][33];
    const int b = blockIdx.z;
    const int s0 = blockIdx.x * 32, a0 = blockIdx.y * 32;
    const int t = threadIdx.x;
    const int r = t >> 3, c = (t & 7) * 4;

    float4 v = *(const float4*)(z + ((long long)b * NS + s0 + r) * NDA + a0 + c);
    __nv_bfloat16 h[4], l[4];
    split_bf16(v.x, h[0], l[0]); split_bf16(v.y, h[1], l[1]);
    split_bf16(v.z, h[2], l[2]); split_bf16(v.w, h[3], l[3]);

    uint2 ph, pl;
    ph.x = pack2(h[0], h[1]); ph.y = pack2(h[2], h[3]);
    pl.x = pack2(l[0], l[1]); pl.y = pack2(l[2], l[3]);
    const long long ro = ((long long)b * SPAD + s0 + r) * NDA + a0 + c;
    *(uint2*)(g_zhi + ro) = ph;
    *(uint2*)(g_zlo + ro) = pl;

#pragma unroll
    for (int i = 0; i < 4; i++) { shi[r][c + i] = h[i]; slo[r][c + i] = l[i]; }
    __syncthreads();

    __nv_bfloat16 th[4], tl[4];
#pragma unroll
    for (int i = 0; i < 4; i++) { th[i] = shi[c + i][r]; tl[i] = slo[c + i][r]; }
    uint2 qh, ql;
    qh.x = pack2(th[0], th[1]); qh.y = pack2(th[2], th[3]);
    ql.x = pack2(tl[0], tl[1]); ql.y = pack2(tl[2], tl[3]);
    const long long to = ((long long)b * NDA + a0 + r) * SPAD + s0 + c;
    *(uint2*)(g_zThi + to) = qh;
    *(uint2*)(g_zTlo + to) = ql;
}

// U fp32 -> bf16 hi/lo (valid region is contiguous prefix of padded buffer)
__global__ __launch_bounds__(256)
void uprep(const float* __restrict__ U)
{
    const long long i = ((long long)blockIdx.x * 256 + threadIdx.x) * 4;
    if (i >= (long long)NL * NDA) return;
    float4 v = *(const float4*)(U + i);
    __nv_bfloat16 h[4], l[4];
    split_bf16(v.x, h[0], l[0]); split_bf16(v.y, h[1], l[1]);
    split_bf16(v.z, h[2], l[2]); split_bf16(v.w, h[3], l[3]);
    uint2 ph, pl;
    ph.x = pack2(h[0], h[1]); ph.y = pack2(h[2], h[3]);
    pl.x = pack2(l[0], l[1]); pl.y = pack2(l[2], l[3]);
    *(uint2*)(g_Uhi + i) = ph;
    *(uint2*)(g_Ulo + i) = pl;
}

// ---------------------------------------------------------------------------
// Softmax over S per (b,l) row; writes fp32 alpha + bf16 hi/lo copies
// ---------------------------------------------------------------------------
__global__ __launch_bounds__(256)
void softmax_kernel(float* __restrict__ alpha)
{
    __shared__ float buf[NS];
    __shared__ float red[8];
    const int bl = blockIdx.x;
    const int b = bl / NL, l = bl % NL;
    float* p = alpha + (long long)bl * NS;
    __nv_bfloat16* ah = g_ahi + ((long long)b * LPAD + l) * SPAD;
    __nv_bfloat16* al = g_alo + ((long long)b * LPAD + l) * SPAD;
    const int t = threadIdx.x;
    const int lane = t & 31, wid = t >> 5;

    float mx = -3.4e38f;
    for (int i = t * 4; i < NS; i += 1024) {
        float4 v = *(const float4*)(p + i);
        *(float4*)(buf + i) = v;
        mx = fmaxf(fmaxf(mx, v.x), fmaxf(fmaxf(v.y, v.z), v.w));
    }
#pragma unroll
    for (int o = 16; o; o >>= 1) mx = fmaxf(mx, __shfl_xor_sync(0xffffffffu, mx, o));
    if (lane == 0) red[wid] = mx;
    __syncthreads();
    if (wid == 0) {
        float m2 = (lane < 8) ? red[lane] : -3.4e38f;
#pragma unroll
        for (int o = 4; o; o >>= 1) m2 = fmaxf(m2, __shfl_xor_sync(0xffffffffu, m2, o));
        if (lane == 0) red[0] = m2;
    }
    __syncthreads();
    mx = red[0];
    __syncthreads();

    float s = 0.f;
    for (int i = t * 4; i < NS; i += 1024) {
        float4 v = *(const float4*)(buf + i);
        v.x = expf(v.x - mx); v.y = expf(v.y - mx);
        v.z = expf(v.z - mx); v.w = expf(v.w - mx);
        *(float4*)(buf + i) = v;
        s += (v.x + v.y) + (v.z + v.w);
    }
#pragma unroll
    for (int o = 16; o; o >>= 1) s += __shfl_xor_sync(0xffffffffu, s, o);
    if (lane == 0) red[wid] = s;
    __syncthreads();
    if (wid == 0) {
        float s2 = (lane < 8) ? red[lane] : 0.f;
#pragma unroll
        for (int o = 4; o; o >>= 1) s2 += __shfl_xor_sync(0xffffffffu, s2, o);
        if (lane == 0) red[0] = s2;
    }
    __syncthreads();
    const float inv = 1.f / red[0];

    for (int i = t * 4; i < NS; i += 1024) {
        float4 v = *(const float4*)(buf + i);
        v.x *= inv; v.y *= inv; v.z *= inv; v.w *= inv;
        *(float4*)(p + i) = v;
        __nv_bfloat16 h[4], lo[4];
        split_bf16(v.x, h[0], lo[0]); split_bf16(v.y, h[1], lo[1]);
        split_bf16(v.z, h[2], lo[2]); split_bf16(v.w, h[3], lo[3]);
        uint2 ph, pl;
        ph.x = pack2(h[0], h[1]); ph.y = pack2(h[2], h[3]);
        pl.x = pack2(lo[0], lo[1]); pl.y = pack2(lo[2], lo[3]);
        *(uint2*)(ah + i) = ph;
        *(uint2*)(al + i) = pl;
    }
}

// ---------------------------------------------------------------------------
// y[b,l] = dot(V[l], m[b,l]) + V_b[l]
// ---------------------------------------------------------------------------
__global__ __launch_bounds__(128)
void y_kernel(const float* __restrict__ Vw, const float* __restrict__ Vb,
              const float* __restrict__ mbuf, float* __restrict__ y)
{
    __shared__ float red[4];
    const int row = blockIdx.x;
    const int l = row % NL;
    const float* mr = mbuf + (long long)row * NDA;
    const float* vr = Vw + (long long)l * NDA;
    const int t = threadIdx.x;

    float s = 0.f;
    for (int i = t; i < NDA; i += 128) s = fmaf(vr[i], mr[i], s);
#pragma unroll
    for (int o = 16; o; o >>= 1) s += __shfl_xor_sync(0xffffffffu, s, o);
    const int lane = t & 31, wid = t >> 5;
    if (lane == 0) red[wid] = s;
    __syncthreads();
    if (t == 0) y[row] = ((red[0] + red[1]) + (red[2] + red[3])) + Vb[l];
}

// ---------------------------------------------------------------------------
extern "C" void kernel_launch(void* const* d_in, const int* in_sizes, int n_in,
                              void* d_out, int out_size)
{
    const float* x  = (const float*)d_in[0];
    const float* Ww = (const float*)d_in[1];
    const float* Wb = (const float*)d_in[2];
    const float* Uw = (const float*)d_in[3];
    const float* Vw = (const float*)d_in[4];
    const float* Vb = (const float*)d_in[5];

    float* y     = (float*)d_out;
    float* alpha = (float*)d_out + (size_t)NB * NL;

    float *zbuf = nullptr, *mbuf = nullptr;
    __nv_bfloat16 *zhi, *zlo, *zThi, *zTlo, *uhi, *ulo, *ahi, *alo;
    cudaGetSymbolAddress((void**)&zbuf, g_z);
    cudaGetSymbolAddress((void**)&mbuf, g_m);
    cudaGetSymbolAddress((void**)&zhi, g_zhi);
    cudaGetSymbolAddress((void**)&zlo, g_zlo);
    cudaGetSymbolAddress((void**)&zThi, g_zThi);
    cudaGetSymbolAddress((void**)&zTlo, g_zTlo);
    cudaGetSymbolAddress((void**)&uhi, g_Uhi);
    cudaGetSymbolAddress((void**)&ulo, g_Ulo);
    cudaGetSymbolAddress((void**)&ahi, g_ahi);
    cudaGetSymbolAddress((void**)&alo, g_alo);

    cudaFuncSetAttribute(gemm_mma, cudaFuncAttributeMaxDynamicSharedMemorySize,
                         2 * STG);

    // 1) z = tanh(x @ W^T + b)  [16000, 512] fp32
    {
        dim3 g(NDA / 128, (NB * NS + 127) / 128, 1);
        gemm_z<<<g, 256>>>(x, Ww, zbuf, Wb, NB * NS, NDA, NDIN);
    }
    // 2) z -> bf16 hi/lo + transposed hi/lo
    {
        dim3 g(NS / 32, NDA / 32, NB);
        zconv<<<g, 256>>>(zbuf);
    }
    // 3) U -> bf16 hi/lo
    {
        long long n4 = (long long)NL * NDA / 4;
        uprep<<<(unsigned)((n4 + 255) / 256), 256>>>(Uw);
    }
    // 4) scores = U @ z^T (bf16x3 mma.sync) -> alpha region of d_out
    {
        dim3 g(SPAD / 128, LPAD / 128, NB);
        gemm_mma<<<g, 256, 2 * STG>>>(
            uhi, ulo, zhi, zlo, alpha,
            NDA / KCH, NL, NS, NDA, NDA, NS,
            0LL, (long long)SPAD * NDA, (long long)NL * NS);
    }
    // 5) softmax (writes fp32 alpha + bf16 hi/lo copies)
    softmax_kernel<<<NB * NL, 256>>>(alpha);

    // 6) m = alpha @ z (bf16x3 mma.sync)
    {
        dim3 g(NDA / 128, LPAD / 128, NB);
        gemm_mma<<<g, 256, 2 * STG>>>(
            ahi, alo, zThi, zTlo, mbuf,
            SPAD / KCH, NL, NDA, SPAD, SPAD, NDA,
            (long long)LPAD * SPAD, (long long)NDA * SPAD, (long long)NL * NDA);
    }
    // 7) y
    y_kernel<<<NB * NL, 128>>>(Vw, Vb, mbuf, y);
}

// round 4
// speedup vs baseline: 2.5542x; 1.2592x over previous
#include <cuda_runtime.h>
#include <cuda_bf16.h>
#include <math.h>
#include <stdint.h>

#define NB 4
#define NS 4000
#define NDIN 1024
#define NDA 512
#define NL 8921
#define SPAD 4096   // padded S
#define LPAD 8960   // padded L (70 * 128)
#define KCH 64      // bf16 K elements per pipeline chunk
#define STG 65536   // bytes per stage: 4 x 16KB buffers (Ahi,Alo,Bhi,Blo)
#define NSTAGE 3

// ---------------------------------------------------------------------------
// Scratch (device globals: zero-initialized at module load; padded regions are
// never written so they stay zero -> no bounds checks in GEMM operand loads).
// ---------------------------------------------------------------------------
__device__ float g_z[(size_t)NB * NS * NDA];
__device__ __nv_bfloat16 g_xhi[(size_t)NB * NS * NDIN];    // x hi  [b*s][din]
__device__ __nv_bfloat16 g_xlo[(size_t)NB * NS * NDIN];
__device__ __nv_bfloat16 g_Whi[(size_t)NDA * NDIN];        // W hi  [a][din]
__device__ __nv_bfloat16 g_Wlo[(size_t)NDA * NDIN];
__device__ __nv_bfloat16 g_zhi[(size_t)NB * SPAD * NDA];   // z hi  [b][s][a]
__device__ __nv_bfloat16 g_zlo[(size_t)NB * SPAD * NDA];
__device__ __nv_bfloat16 g_zThi[(size_t)NB * NDA * SPAD];  // z^T hi [b][a][s]
__device__ __nv_bfloat16 g_zTlo[(size_t)NB * NDA * SPAD];
__device__ __nv_bfloat16 g_Uhi[(size_t)LPAD * NDA];
__device__ __nv_bfloat16 g_Ulo[(size_t)LPAD * NDA];
__device__ __nv_bfloat16 g_ahi[(size_t)NB * LPAD * SPAD];  // alpha hi (padded)
__device__ __nv_bfloat16 g_alo[(size_t)NB * LPAD * SPAD];
__device__ float g_m[(size_t)NB * NL * NDA];

// ---------------------------------------------------------------------------
// Helpers
// ---------------------------------------------------------------------------
__device__ __forceinline__ uint32_t smem_u32(const void* p) {
    uint32_t a;
    asm("{ .reg .u64 t; cvta.to.shared.u64 t, %1; cvt.u32.u64 %0, t; }"
        : "=r"(a) : "l"(p));
    return a;
}
__device__ __forceinline__ void cpa16(uint32_t dst, const void* src) {
    asm volatile("cp.async.cg.shared.global [%0], [%1], 16;"
                 :: "r"(dst), "l"(src) : "memory");
}
#define CP_COMMIT() asm volatile("cp.async.commit_group;" ::: "memory")
#define CP_WAIT(n)  asm volatile("cp.async.wait_group %0;" :: "n"(n) : "memory")

__device__ __forceinline__ void ldsm4(uint32_t& r0, uint32_t& r1,
                                      uint32_t& r2, uint32_t& r3, uint32_t addr) {
    asm volatile("ldmatrix.sync.aligned.m8n8.x4.shared.b16 {%0,%1,%2,%3}, [%4];"
                 : "=r"(r0), "=r"(r1), "=r"(r2), "=r"(r3) : "r"(addr));
}
__device__ __forceinline__ void mma16816(float* d, const uint32_t* a, const uint32_t* b) {
    asm volatile(
        "mma.sync.aligned.m16n8k16.row.col.f32.bf16.bf16.f32 "
        "{%0,%1,%2,%3}, {%4,%5,%6,%7}, {%8,%9}, {%0,%1,%2,%3};"
        : "+f"(d[0]), "+f"(d[1]), "+f"(d[2]), "+f"(d[3])
        : "r"(a[0]), "r"(a[1]), "r"(a[2]), "r"(a[3]), "r"(b[0]), "r"(b[1]));
}

__device__ __forceinline__ void split_bf16(float v, __nv_bfloat16& hi, __nv_bfloat16& lo) {
    hi = __float2bfloat16(v);
    lo = __float2bfloat16(v - __bfloat162float(hi));
}
__device__ __forceinline__ uint32_t pack2(__nv_bfloat16 a, __nv_bfloat16 b) {
    return (uint32_t)__bfloat16_as_ushort(a) | ((uint32_t)__bfloat16_as_ushort(b) << 16);
}

// Swizzled offset inside a 128-row x 64-col bf16 buffer (128B rows, 8 x 16B
// groups, group ^= row&7 -> ldmatrix phases and cp.async writes conflict-free).
__device__ __forceinline__ uint32_t swoff(int row, int c16) {
    return (uint32_t)(row * 128 + ((c16 ^ (row & 7)) * 16));
}

// ---------------------------------------------------------------------------
// bf16x3 tensor-core GEMM via mma.sync:
//   D[M,N] = sum_k (Ahi+Alo)[m,k]*(Bhi+Blo)[n,k]   (Alo*Blo dropped)
// CTA tile 128x128, 8 warps (2x4), warp tile 64x32, K-chunk 64,
// 3-stage cp.async pipeline, ONE __syncthreads per chunk.
// Optional epilogue: tanh(acc + bias[n]).
// ---------------------------------------------------------------------------
template <bool TANH>
__global__ __launch_bounds__(256, 1)
void gemm_mma(const __nv_bfloat16* __restrict__ Ahi, const __nv_bfloat16* __restrict__ Alo,
              const __nv_bfloat16* __restrict__ Bhi, const __nv_bfloat16* __restrict__ Blo,
              float* __restrict__ C, const float* __restrict__ bias,
              int nk, int Mvalid, int Nvalid, int ldA, int ldB, int ldC,
              long long sA, long long sB, long long sC)
{
    extern __shared__ char smem[];
    const uint32_t sb = smem_u32(smem);

    const int t = threadIdx.x, w = t >> 5, lane = t & 31;
    const int m0 = blockIdx.y * 128, n0 = blockIdx.x * 128, b = blockIdx.z;
    const int wm = (w >> 2) * 64, wn = (w & 3) * 32;

    const __nv_bfloat16* Ah = Ahi + b * sA + (long long)m0 * ldA;
    const __nv_bfloat16* Al = Alo + b * sA + (long long)m0 * ldA;
    const __nv_bfloat16* Bh = Bhi + b * sB + (long long)n0 * ldB;
    const __nv_bfloat16* Bl = Blo + b * sB + (long long)n0 * ldB;
    float* Cb = C + b * sC;

    float acc[4][4][4];
#pragma unroll
    for (int i = 0; i < 4; i++)
#pragma unroll
        for (int j = 0; j < 4; j++)
#pragma unroll
            for (int q = 0; q < 4; q++) acc[i][j][q] = 0.f;

    // stage layout: +0 Ahi, +16K Alo, +32K Bhi, +48K Blo  (each 128x64 bf16)
    auto load_stage = [&](int c, int s) {
        const uint32_t st = sb + s * STG;
        const int kb = c * KCH;
#pragma unroll
        for (int j = 0; j < 4; j++) {
            const int cid = t + 256 * j;                 // 0..1023
            const int row = cid >> 3, c16 = cid & 7;
            const uint32_t sw = swoff(row, c16);
            const long long ga = (long long)row * ldA + kb + c16 * 8;
            const long long gb = (long long)row * ldB + kb + c16 * 8;
            cpa16(st + sw,             Ah + ga);
            cpa16(st + 16384 + sw,     Al + ga);
            cpa16(st + 32768 + sw,     Bh + gb);
            cpa16(st + 49152 + sw,     Bl + gb);
        }
    };

    load_stage(0, 0); CP_COMMIT();
    load_stage(1, 1); CP_COMMIT();

    for (int c = 0; c < nk; c++) {
        const int s = c % NSTAGE;
        if (c == nk - 1) { CP_WAIT(0); } else { CP_WAIT(1); }
        __syncthreads();           // stage s published; stage (c+2)%3 free
        if (c + 2 < nk) { load_stage(c + 2, (c + 2) % NSTAGE); CP_COMMIT(); }

        const uint32_t stAh = sb + s * STG;
        const uint32_t stAl = stAh + 16384;
        const uint32_t stBh = stAh + 32768;
        const uint32_t stBl = stAh + 49152;

#pragma unroll
        for (int kk = 0; kk < 4; kk++) {
            uint32_t ah[4][4], al[4][4];
            {
                const int r = lane & 15, ch = lane >> 4;
#pragma unroll
                for (int mt = 0; mt < 4; mt++) {
                    const uint32_t off = swoff(wm + mt * 16 + r, kk * 2 + ch);
                    ldsm4(ah[mt][0], ah[mt][1], ah[mt][2], ah[mt][3], stAh + off);
                    ldsm4(al[mt][0], al[mt][1], al[mt][2], al[mt][3], stAl + off);
                }
            }
            uint32_t bh[4][2], bl[4][2];
            {
                const int r8 = ((lane >> 4) << 3) + (lane & 7);
                const int ch = (lane >> 3) & 1;
#pragma unroll
                for (int nh = 0; nh < 2; nh++) {
                    const uint32_t off = swoff(wn + nh * 16 + r8, kk * 2 + ch);
                    uint32_t r0, r1, r2, r3;
                    ldsm4(r0, r1, r2, r3, stBh + off);
                    bh[nh * 2][0] = r0; bh[nh * 2][1] = r1;
                    bh[nh * 2 + 1][0] = r2; bh[nh * 2 + 1][1] = r3;
                    ldsm4(r0, r1, r2, r3, stBl + off);
                    bl[nh * 2][0] = r0; bl[nh * 2][1] = r1;
                    bl[nh * 2 + 1][0] = r2; bl[nh * 2 + 1][1] = r3;
                }
            }
#pragma unroll
            for (int mt = 0; mt < 4; mt++)
#pragma unroll
                for (int nt = 0; nt < 4; nt++) {
                    mma16816(acc[mt][nt], ah[mt], bh[nt]);
                    mma16816(acc[mt][nt], al[mt], bh[nt]);
                    mma16816(acc[mt][nt], ah[mt], bl[nt]);
                }
        }
    }

    // Epilogue
#pragma unroll
    for (int mt = 0; mt < 4; mt++) {
        const int r0g = m0 + wm + mt * 16 + (lane >> 2);
        const int r1g = r0g + 8;
#pragma unroll
        for (int nt = 0; nt < 4; nt++) {
            const int cg = n0 + wn + nt * 8 + (lane & 3) * 2;
            if (cg < Nvalid) {
                float2 v0 = make_float2(acc[mt][nt][0], acc[mt][nt][1]);
                float2 v1 = make_float2(acc[mt][nt][2], acc[mt][nt][3]);
                if (TANH) {
                    const float b0v = bias[cg], b1v = bias[cg + 1];
                    v0.x = tanhf(v0.x + b0v); v0.y = tanhf(v0.y + b1v);
                    v1.x = tanhf(v1.x + b0v); v1.y = tanhf(v1.y + b1v);
                }
                if (r0g < Mvalid) *(float2*)(Cb + (long long)r0g * ldC + cg) = v0;
                if (r1g < Mvalid) *(float2*)(Cb + (long long)r1g * ldC + cg) = v1;
            }
        }
    }
}

// ---------------------------------------------------------------------------
// fp32 -> bf16 hi/lo flat splitters
// ---------------------------------------------------------------------------
__global__ __launch_bounds__(256)
void split_flat(const float* __restrict__ src, __nv_bfloat16* __restrict__ dhi,
                __nv_bfloat16* __restrict__ dlo, long long n)
{
    const long long i = ((long long)blockIdx.x * 256 + threadIdx.x) * 4;
    if (i >= n) return;
    float4 v = *(const float4*)(src + i);
    __nv_bfloat16 h[4], l[4];
    split_bf16(v.x, h[0], l[0]); split_bf16(v.y, h[1], l[1]);
    split_bf16(v.z, h[2], l[2]); split_bf16(v.w, h[3], l[3]);
    uint2 ph, pl;
    ph.x = pack2(h[0], h[1]); ph.y = pack2(h[2], h[3]);
    pl.x = pack2(l[0], l[1]); pl.y = pack2(l[2], l[3]);
    *(uint2*)(dhi + i) = ph;
    *(uint2*)(dlo + i) = pl;
}

// ---------------------------------------------------------------------------
// z fp32 -> bf16 hi/lo (padded row-major) + transposed hi/lo
// ---------------------------------------------------------------------------
__global__ __launch_bounds__(256)
void zconv(const float* __restrict__ z)
{
    __shared__ __nv_bfloat16 shi[32][33];
    __shared__ __nv_bfloat16 slo[32][33];
    const int b = blockIdx.z;
    const int s0 = blockIdx.x * 32, a0 = blockIdx.y * 32;
    const int t = threadIdx.x;
    const int r = t >> 3, c = (t & 7) * 4;

    float4 v = *(const float4*)(z + ((long long)b * NS + s0 + r) * NDA + a0 + c);
    __nv_bfloat16 h[4], l[4];
    split_bf16(v.x, h[0], l[0]); split_bf16(v.y, h[1], l[1]);
    split_bf16(v.z, h[2], l[2]); split_bf16(v.w, h[3], l[3]);

    uint2 ph, pl;
    ph.x = pack2(h[0], h[1]); ph.y = pack2(h[2], h[3]);
    pl.x = pack2(l[0], l[1]); pl.y = pack2(l[2], l[3]);
    const long long ro = ((long long)b * SPAD + s0 + r) * NDA + a0 + c;
    *(uint2*)(g_zhi + ro) = ph;
    *(uint2*)(g_zlo + ro) = pl;

#pragma unroll
    for (int i = 0; i < 4; i++) { shi[r][c + i] = h[i]; slo[r][c + i] = l[i]; }
    __syncthreads();

    __nv_bfloat16 th[4], tl[4];
#pragma unroll
    for (int i = 0; i < 4; i++) { th[i] = shi[c + i][r]; tl[i] = slo[c + i][r]; }
    uint2 qh, ql;
    qh.x = pack2(th[0], th[1]); qh.y = pack2(th[2], th[3]);
    ql.x = pack2(tl[0], tl[1]); ql.y = pack2(tl[2], tl[3]);
    const long long to = ((long long)b * NDA + a0 + r) * SPAD + s0 + c;
    *(uint2*)(g_zThi + to) = qh;
    *(uint2*)(g_zTlo + to) = ql;
}

// ---------------------------------------------------------------------------
// Softmax over S per (b,l) row; writes fp32 alpha + bf16 hi/lo copies
// ---------------------------------------------------------------------------
__global__ __launch_bounds__(256)
void softmax_kernel(float* __restrict__ alpha)
{
    __shared__ float buf[NS];
    __shared__ float red[8];
    const int bl = blockIdx.x;
    const int b = bl / NL, l = bl % NL;
    float* p = alpha + (long long)bl * NS;
    __nv_bfloat16* ah = g_ahi + ((long long)b * LPAD + l) * SPAD;
    __nv_bfloat16* al = g_alo + ((long long)b * LPAD + l) * SPAD;
    const int t = threadIdx.x;
    const int lane = t & 31, wid = t >> 5;

    float mx = -3.4e38f;
    for (int i = t * 4; i < NS; i += 1024) {
        float4 v = *(const float4*)(p + i);
        *(float4*)(buf + i) = v;
        mx = fmaxf(fmaxf(mx, v.x), fmaxf(fmaxf(v.y, v.z), v.w));
    }
#pragma unroll
    for (int o = 16; o; o >>= 1) mx = fmaxf(mx, __shfl_xor_sync(0xffffffffu, mx, o));
    if (lane == 0) red[wid] = mx;
    __syncthreads();
    if (wid == 0) {
        float m2 = (lane < 8) ? red[lane] : -3.4e38f;
#pragma unroll
        for (int o = 4; o; o >>= 1) m2 = fmaxf(m2, __shfl_xor_sync(0xffffffffu, m2, o));
        if (lane == 0) red[0] = m2;
    }
    __syncthreads();
    mx = red[0];
    __syncthreads();

    float s = 0.f;
    for (int i = t * 4; i < NS; i += 1024) {
        float4 v = *(const float4*)(buf + i);
        v.x = __expf(v.x - mx); v.y = __expf(v.y - mx);
        v.z = __expf(v.z - mx); v.w = __expf(v.w - mx);
        *(float4*)(buf + i) = v;
        s += (v.x + v.y) + (v.z + v.w);
    }
#pragma unroll
    for (int o = 16; o; o >>= 1) s += __shfl_xor_sync(0xffffffffu, s, o);
    if (lane == 0) red[wid] = s;
    __syncthreads();
    if (wid == 0) {
        float s2 = (lane < 8) ? red[lane] : 0.f;
#pragma unroll
        for (int o = 4; o; o >>= 1) s2 += __shfl_xor_sync(0xffffffffu, s2, o);
        if (lane == 0) red[0] = s2;
    }
    __syncthreads();
    const float inv = 1.f / red[0];

    for (int i = t * 4; i < NS; i += 1024) {
        float4 v = *(const float4*)(buf + i);
        v.x *= inv; v.y *= inv; v.z *= inv; v.w *= inv;
        *(float4*)(p + i) = v;
        __nv_bfloat16 h[4], lo[4];
        split_bf16(v.x, h[0], lo[0]); split_bf16(v.y, h[1], lo[1]);
        split_bf16(v.z, h[2], lo[2]); split_bf16(v.w, h[3], lo[3]);
        uint2 ph, pl;
        ph.x = pack2(h[0], h[1]); ph.y = pack2(h[2], h[3]);
        pl.x = pack2(lo[0], lo[1]); pl.y = pack2(lo[2], lo[3]);
        *(uint2*)(ah + i) = ph;
        *(uint2*)(al + i) = pl;
    }
}

// ---------------------------------------------------------------------------
// y[b,l] = dot(V[l], m[b,l]) + V_b[l]
// ---------------------------------------------------------------------------
__global__ __launch_bounds__(128)
void y_kernel(const float* __restrict__ Vw, const float* __restrict__ Vb,
              const float* __restrict__ mbuf, float* __restrict__ y)
{
    __shared__ float red[4];
    const int row = blockIdx.x;
    const int l = row % NL;
    const float* mr = mbuf + (long long)row * NDA;
    const float* vr = Vw + (long long)l * NDA;
    const int t = threadIdx.x;

    float s = 0.f;
    for (int i = t; i < NDA; i += 128) s = fmaf(vr[i], mr[i], s);
#pragma unroll
    for (int o = 16; o; o >>= 1) s += __shfl_xor_sync(0xffffffffu, s, o);
    const int lane = t & 31, wid = t >> 5;
    if (lane == 0) red[wid] = s;
    __syncthreads();
    if (t == 0) y[row] = ((red[0] + red[1]) + (red[2] + red[3])) + Vb[l];
}

// ---------------------------------------------------------------------------
extern "C" void kernel_launch(void* const* d_in, const int* in_sizes, int n_in,
                              void* d_out, int out_size)
{
    const float* x  = (const float*)d_in[0];
    const float* Ww = (const float*)d_in[1];
    const float* Wb = (const float*)d_in[2];
    const float* Uw = (const float*)d_in[3];
    const float* Vw = (const float*)d_in[4];
    const float* Vb = (const float*)d_in[5];

    float* y     = (float*)d_out;
    float* alpha = (float*)d_out + (size_t)NB * NL;

    float *zbuf, *mbuf;
    __nv_bfloat16 *xhi, *xlo, *whi, *wlo, *zhi, *zlo, *zThi, *zTlo, *uhi, *ulo, *ahi, *alo;
    cudaGetSymbolAddress((void**)&zbuf, g_z);
    cudaGetSymbolAddress((void**)&mbuf, g_m);
    cudaGetSymbolAddress((void**)&xhi, g_xhi);
    cudaGetSymbolAddress((void**)&xlo, g_xlo);
    cudaGetSymbolAddress((void**)&whi, g_Whi);
    cudaGetSymbolAddress((void**)&wlo, g_Wlo);
    cudaGetSymbolAddress((void**)&zhi, g_zhi);
    cudaGetSymbolAddress((void**)&zlo, g_zlo);
    cudaGetSymbolAddress((void**)&zThi, g_zThi);
    cudaGetSymbolAddress((void**)&zTlo, g_zTlo);
    cudaGetSymbolAddress((void**)&uhi, g_Uhi);
    cudaGetSymbolAddress((void**)&ulo, g_Ulo);
    cudaGetSymbolAddress((void**)&ahi, g_ahi);
    cudaGetSymbolAddress((void**)&alo, g_alo);

    cudaFuncSetAttribute(gemm_mma<false>, cudaFuncAttributeMaxDynamicSharedMemorySize,
                         NSTAGE * STG);
    cudaFuncSetAttribute(gemm_mma<true>, cudaFuncAttributeMaxDynamicSharedMemorySize,
                         NSTAGE * STG);

    // 1) split x and W into bf16 hi/lo
    {
        long long nx = (long long)NB * NS * NDIN;
        split_flat<<<(unsigned)((nx / 4 + 255) / 256), 256>>>(x, xhi, xlo, nx);
        long long nw = (long long)NDA * NDIN;
        split_flat<<<(unsigned)((nw / 4 + 255) / 256), 256>>>(Ww, whi, wlo, nw);
    }
    // 2) split U into bf16 hi/lo
    {
        long long nu = (long long)NL * NDA;
        split_flat<<<(unsigned)((nu / 4 + 255) / 256), 256>>>(Uw, uhi, ulo, nu);
    }
    // 3) z = tanh(x @ W^T + b)  via bf16x3 MMA  [16000, 512]
    {
        dim3 g(NDA / 128, (NB * NS) / 128, 1);
        gemm_mma<true><<<g, 256, NSTAGE * STG>>>(
            xhi, xlo, whi, wlo, zbuf, Wb,
            NDIN / KCH, NB * NS, NDA, NDIN, NDIN, NDA, 0LL, 0LL, 0LL);
    }
    // 4) z -> bf16 hi/lo + transposed hi/lo
    {
        dim3 g(NS / 32, NDA / 32, NB);
        zconv<<<g, 256>>>(zbuf);
    }
    // 5) scores = U @ z^T (bf16x3) -> alpha region of d_out
    {
        dim3 g(SPAD / 128, LPAD / 128, NB);
        gemm_mma<false><<<g, 256, NSTAGE * STG>>>(
            uhi, ulo, zhi, zlo, alpha, nullptr,
            NDA / KCH, NL, NS, NDA, NDA, NS,
            0LL, (long long)SPAD * NDA, (long long)NL * NS);
    }
    // 6) softmax (writes fp32 alpha + bf16 hi/lo copies)
    softmax_kernel<<<NB * NL, 256>>>(alpha);

    // 7) m = alpha @ z (bf16x3)
    {
        dim3 g(NDA / 128, LPAD / 128, NB);
        gemm_mma<false><<<g, 256, NSTAGE * STG>>>(
            ahi, alo, zThi, zTlo, mbuf, nullptr,
            SPAD / KCH, NL, NDA, SPAD, SPAD, NDA,
            (long long)LPAD * SPAD, (long long)NDA * SPAD, (long long)NL * NDA);
    }
    // 8) y
    y_kernel<<<NB * NL, 128>>>(Vw, Vb, mbuf, y);
}